// round 14
// baseline (speedup 1.0000x reference)
#include <cuda_runtime.h>
#include <math_constants.h>

// Problem constants (fixed by the reference)
#define Nn 100000
#define Ee 3200000
#define EN (Ee + Nn)      // edges + self loops
#define Hh 32
#define Ff 128
#define Bb 256
#define D1 1024
#define D2 512
#define D3 4
#define NB 98             // scan blocks: ceil(100000/1024)

// ---------------- scratch (static device globals; no allocation) -----------
// d_deg and d_g are zero at load; every kernel_launch call restores them to
// zero before finishing (k_node zeros d_deg, k_mlp1 zeros d_g) so graph
// replays are deterministic.
__device__ float        d_xl[Nn * Hh];       // x @ Wl
__device__ float        d_xr[Nn * Hh];       // x @ Wr
__device__ int          d_deg[Nn];           // raw in-degree (no self loop)
__device__ int          d_rowstart[Nn];      // CSR row offsets
__device__ int          d_cursor[Nn];        // fill cursors
__device__ int          d_csrc[EN];          // CSR source indices (by dst)
__device__ unsigned int d_g[Bb * Hh];        // pooled max per graph (encoded)
__device__ float        d_h1[Bb * D1];
__device__ float        d_h2[Bb * D2];

// order-preserving float<->unsigned encoding for atomicMax on floats.
// All real floats encode to >= 0x007FFFFF > 0, so zero-init is a valid
// "-inf" sentinel for atomicMax.
__device__ __forceinline__ unsigned int fenc(float f) {
    unsigned int u = __float_as_uint(f);
    return u ^ ((unsigned int)((int)u >> 31) | 0x80000000u);
}
__device__ __forceinline__ float fdec(unsigned int e) {
    unsigned int mask = ((int)e < 0) ? 0x80000000u : 0xFFFFFFFFu;
    return __uint_as_float(e ^ mask);
}

__device__ __forceinline__ int wscan_incl(int v, int lane) {
#pragma unroll
    for (int off = 1; off < 32; off <<= 1) {
        int n = __shfl_up_sync(0xFFFFFFFFu, v, off);
        if (lane >= off) v += n;
    }
    return v;
}

// ---------------- kernels ---------------------------------------------------

// degree histogram: 16 edges per thread (4x int4), fire-and-forget RED
__global__ void __launch_bounds__(256) k_count(const int* __restrict__ ei) {
    int i16 = blockIdx.x * blockDim.x + threadIdx.x;   // 0 .. Ee/16
    if (i16 >= Ee / 16) return;
    const int4* d4 = (const int4*)(ei + Ee);
#pragma unroll
    for (int j = 0; j < 4; j++) {
        int4 a = d4[i16 * 4 + j];
        atomicAdd(&d_deg[a.x], 1);
        atomicAdd(&d_deg[a.y], 1);
        atomicAdd(&d_deg[a.z], 1);
        atomicAdd(&d_deg[a.w], 1);
    }
}

// Single-kernel scan: each block recomputes its global prefix directly from
// raw d_deg (self-loops folded as +1/node), then intra-block scan ->
// rowstart, self-loop slot, cursor.
__global__ void __launch_bounds__(1024) k_scan() {
    __shared__ int wsum[32];
    __shared__ int s_pre;
    int t = threadIdx.x, lane = t & 31, w = t >> 5;
    int blockStart = blockIdx.x * 1024;
    int idx = blockStart + t;

    // prefix over preceding chunk: sum(deg[0..blockStart)) + blockStart (self loops)
    int a = 0;
    for (int k = t; k < blockStart; k += 1024) a += d_deg[k];
#pragma unroll
    for (int off = 16; off; off >>= 1) a += __shfl_xor_sync(0xFFFFFFFFu, a, off);
    if (lane == 0) wsum[w] = a;
    __syncthreads();
    if (w == 0) {
        int s = wsum[lane];
#pragma unroll
        for (int off = 16; off; off >>= 1) s += __shfl_xor_sync(0xFFFFFFFFu, s, off);
        if (lane == 0) s_pre = s + blockStart;
    }
    __syncthreads();

    int v = (idx < Nn) ? d_deg[idx] + 1 : 0;    // +1 self loop
    int incl = wscan_incl(v, lane);
    __syncthreads();
    if (lane == 31) wsum[w] = incl;
    __syncthreads();
    if (w == 0) wsum[lane] = wscan_incl(wsum[lane], lane);
    __syncthreads();
    int off = s_pre + ((w > 0) ? wsum[w - 1] : 0);
    int excl = off + incl - v;
    if (idx < Nn) {
        d_rowstart[idx] = excl;
        d_csrc[excl]    = idx;       // self loop first
        d_cursor[idx]   = excl + 1;
    }
}

// xl|xr = x @ [Wl|Wr]: 64 nodes x 64 cols per block, 256 threads,
// K processed in two 64-wide chunks -> 32KB smem -> high occupancy.
__global__ void __launch_bounds__(256) k_transform(
    const float* __restrict__ x,
    const float* __restrict__ Wl,
    const float* __restrict__ Wr)
{
    __shared__ float sW[64 * 64];   // [k_chunk][c]  16KB
    __shared__ float sx[64 * 64];   // [n][k_chunk]  16KB

    int t = threadIdx.x;
    int n0 = blockIdx.x * 64;               // grid 1563; last block ragged
    int tx = t & 15, ty = t >> 4;           // 16 x 16 thread grid
    int c0 = tx * 4;

    float acc[4][4] = {};

#pragma unroll
    for (int kc = 0; kc < 2; kc++) {
        int k0 = kc * 64;
        // load W chunk [64 x 64]
        for (int i = t; i < 64 * 64; i += 256) {
            int k = i >> 6, c = i & 63;
            sW[i] = (c < 32) ? Wl[(k0 + k) * Hh + c] : Wr[(k0 + k) * Hh + (c - 32)];
        }
        // load x chunk: 64 rows x 16 float4 (clamp ragged rows)
        {
            int f4 = t & 15;
            int rbase = t >> 4;
#pragma unroll
            for (int j = 0; j < 4; j++) {
                int r = rbase + j * 16;
                int row = min(n0 + r, Nn - 1);
                ((float4*)sx)[r * 16 + f4] =
                    *(const float4*)&x[(size_t)row * Ff + k0 + f4 * 4];
            }
        }
        __syncthreads();

        const float4* sW4 = (const float4*)sW;
        const float4* sx4 = (const float4*)sx;
#pragma unroll 4
        for (int k4 = 0; k4 < 16; k4++) {
            float4 w0 = sW4[(k4 * 4 + 0) * 16 + tx];
            float4 w1 = sW4[(k4 * 4 + 1) * 16 + tx];
            float4 w2 = sW4[(k4 * 4 + 2) * 16 + tx];
            float4 w3 = sW4[(k4 * 4 + 3) * 16 + tx];
#pragma unroll
            for (int i = 0; i < 4; i++) {
                float4 xv = sx4[(ty * 4 + i) * 16 + k4];
                acc[i][0] += xv.x * w0.x + xv.y * w1.x + xv.z * w2.x + xv.w * w3.x;
                acc[i][1] += xv.x * w0.y + xv.y * w1.y + xv.z * w2.y + xv.w * w3.y;
                acc[i][2] += xv.x * w0.z + xv.y * w1.z + xv.z * w2.z + xv.w * w3.z;
                acc[i][3] += xv.x * w0.w + xv.y * w1.w + xv.z * w2.w + xv.w * w3.w;
            }
        }
        __syncthreads();
    }

#pragma unroll
    for (int i = 0; i < 4; i++) {
        int node = n0 + ty * 4 + i;
        if (node < Nn) {
            float4 v = make_float4(acc[i][0], acc[i][1], acc[i][2], acc[i][3]);
            if (c0 < 32) *(float4*)&d_xl[node * Hh + c0] = v;
            else         *(float4*)&d_xr[node * Hh + (c0 - 32)] = v;
        }
    }
}

// scatter real edges into CSR order: 16 edges per thread, 16 atomics in flight
__global__ void __launch_bounds__(256) k_fill(const int* __restrict__ ei) {
    int i16 = blockIdx.x * blockDim.x + threadIdx.x;
    if (i16 >= Ee / 16) return;
    const int4* s4 = (const int4*)ei;
    const int4* d4 = (const int4*)(ei + Ee);
    int4 sa = s4[i16 * 4 + 0], sb = s4[i16 * 4 + 1];
    int4 sc = s4[i16 * 4 + 2], sd = s4[i16 * 4 + 3];
    int4 da = d4[i16 * 4 + 0], db = d4[i16 * 4 + 1];
    int4 dc = d4[i16 * 4 + 2], dd = d4[i16 * 4 + 3];
    int p0  = atomicAdd(&d_cursor[da.x], 1);
    int p1  = atomicAdd(&d_cursor[da.y], 1);
    int p2  = atomicAdd(&d_cursor[da.z], 1);
    int p3  = atomicAdd(&d_cursor[da.w], 1);
    int p4  = atomicAdd(&d_cursor[db.x], 1);
    int p5  = atomicAdd(&d_cursor[db.y], 1);
    int p6  = atomicAdd(&d_cursor[db.z], 1);
    int p7  = atomicAdd(&d_cursor[db.w], 1);
    int p8  = atomicAdd(&d_cursor[dc.x], 1);
    int p9  = atomicAdd(&d_cursor[dc.y], 1);
    int p10 = atomicAdd(&d_cursor[dc.z], 1);
    int p11 = atomicAdd(&d_cursor[dc.w], 1);
    int p12 = atomicAdd(&d_cursor[dd.x], 1);
    int p13 = atomicAdd(&d_cursor[dd.y], 1);
    int p14 = atomicAdd(&d_cursor[dd.z], 1);
    int p15 = atomicAdd(&d_cursor[dd.w], 1);
    d_csrc[p0]  = sa.x;  d_csrc[p1]  = sa.y;
    d_csrc[p2]  = sa.z;  d_csrc[p3]  = sa.w;
    d_csrc[p4]  = sb.x;  d_csrc[p5]  = sb.y;
    d_csrc[p6]  = sb.z;  d_csrc[p7]  = sb.w;
    d_csrc[p8]  = sc.x;  d_csrc[p9]  = sc.y;
    d_csrc[p10] = sc.z;  d_csrc[p11] = sc.w;
    d_csrc[p12] = sd.x;  d_csrc[p13] = sd.y;
    d_csrc[p14] = sd.z;  d_csrc[p15] = sd.w;
}

// Fused GATv2 edge phase v8: register tiles, csrc prefetch, 2-shuffle tile
// max. One warp per node; lane (g = row-subgroup, q = h-quad).
__global__ void __launch_bounds__(256, 4) k_node(
    const float* __restrict__ att, const int* __restrict__ batch)
{
    int t = threadIdx.x;
    int lane = t & 31;
    int w = t >> 5;

    int node = blockIdx.x * 8 + w;          // Nn % 8 == 0
    int beg = d_rowstart[node];
    int deg = d_deg[node];
    int end = beg + deg + 1;                // +1 self loop
    if (lane == 0) d_deg[node] = 0;         // restore for next replay

    int q = lane & 7;           // h-quad (h = 4q..4q+3)
    int g = lane >> 3;          // row subgroup 0..3
    float4 xr4  = *(const float4*)&d_xr[node * Hh + q * 4];
    float4 att4 = __ldg((const float4*)&att[q * 4]);

    float m = -CUDART_INF_F, zsum = 0.f;
    float4 acc = make_float4(0.f, 0.f, 0.f, 0.f);

    int myidx0 = beg + lane;
    int msrc = (myidx0 < end) ? __ldg(&d_csrc[myidx0]) : 0;

    for (int j0 = beg; j0 < end; j0 += 32) {
        int cnt = end - j0;                  // valid rows are r < cnt

        // prefetch next tile's sources (off the critical path)
        int nidx = j0 + 32 + lane;
        int msrc_next = (nidx < end) ? __ldg(&d_csrc[nidx]) : 0;

        // ---- stage into registers: 8 independent LDG.128 ----
        float4 v[8];
#pragma unroll
        for (int i = 0; i < 8; i++) {
            int r = i * 4 + g;
            int src = __shfl_sync(0xFFFFFFFFu, msrc, r);
            v[i] = make_float4(0.f, 0.f, 0.f, 0.f);
            if (r < cnt) v[i] = *(const float4*)&d_xl[src * Hh + q * 4];
        }

        // ---- partial scores from this lane's quad ----
        float s[8];
#pragma unroll
        for (int i = 0; i < 8; i++) {
            float u, sc;
            float a0 = v[i].x + xr4.x; u = fmaxf(a0, 0.2f * a0); sc  = u * att4.x;
            float a1 = v[i].y + xr4.y; u = fmaxf(a1, 0.2f * a1); sc += u * att4.y;
            float a2 = v[i].z + xr4.z; u = fmaxf(a2, 0.2f * a2); sc += u * att4.z;
            float a3 = v[i].w + xr4.w; u = fmaxf(a3, 0.2f * a3); sc += u * att4.w;
            s[i] = sc;
        }
        // reduce across the 8 q-lanes sharing this g (xor 1,2,4)
#pragma unroll
        for (int off = 1; off <= 4; off <<= 1) {
#pragma unroll
            for (int i = 0; i < 8; i++)
                s[i] += __shfl_xor_sync(0xFFFFFFFFu, s[i], off);
        }
        // mask invalid rows
#pragma unroll
        for (int i = 0; i < 8; i++)
            if (i * 4 + g >= cnt) s[i] = -CUDART_INF_F;

        // ---- tile max: scores q-duplicated -> local max + cross-g xor 8,16 ----
        float mt = s[0];
#pragma unroll
        for (int i = 1; i < 8; i++) mt = fmaxf(mt, s[i]);
        mt = fmaxf(mt, __shfl_xor_sync(0xFFFFFFFFu, mt, 8));
        mt = fmaxf(mt, __shfl_xor_sync(0xFFFFFFFFu, mt, 16));
        float mnew = fmaxf(m, mt);
        float scale = __expf(m - mnew);      // first tile: exp(-inf)=0

        // ---- exp + z ----
        float zp = 0.f;
#pragma unroll
        for (int i = 0; i < 8; i++) {
            float p = __expf(s[i] - mnew);   // masked rows -> 0
            s[i] = p;
            zp += p;
        }
        zp += __shfl_xor_sync(0xFFFFFFFFu, zp, 8);
        zp += __shfl_xor_sync(0xFFFFFFFFu, zp, 16);
        zsum = zsum * scale + zp;

        // ---- aggregate in registers ----
        acc.x *= scale; acc.y *= scale; acc.z *= scale; acc.w *= scale;
#pragma unroll
        for (int i = 0; i < 8; i++) {
            acc.x += s[i] * v[i].x;
            acc.y += s[i] * v[i].y;
            acc.z += s[i] * v[i].z;
            acc.w += s[i] * v[i].w;
        }
        m = mnew;
        msrc = msrc_next;
    }

    // combine across row subgroups (lanes l, l^8, l^16 share quad q)
#pragma unroll
    for (int off = 8; off <= 16; off <<= 1) {
        acc.x += __shfl_xor_sync(0xFFFFFFFFu, acc.x, off);
        acc.y += __shfl_xor_sync(0xFFFFFFFFu, acc.y, off);
        acc.z += __shfl_xor_sync(0xFFFFFFFFu, acc.z, off);
        acc.w += __shfl_xor_sync(0xFFFFFFFFu, acc.w, off);
    }
    float inv = 1.0f / zsum;
    float compo = (g == 0) ? acc.x : (g == 1) ? acc.y : (g == 2) ? acc.z : acc.w;
    float out = compo * inv;                 // acc holds p*xl directly
    int h = q * 4 + g;
    int bg = __ldg(&batch[node]);
    atomicMax(&d_g[bg * Hh + h], fenc(out));
}

// h1 = relu((g + bias) @ W1 + b1); also restores d_g to 0 for next replay
__global__ void __launch_bounds__(1024) k_mlp1(
    const float* __restrict__ W1, const float* __restrict__ b1,
    const float* __restrict__ bias)
{
    __shared__ float sg[Hh];
    int b = blockIdx.x;
    int j = threadIdx.x;
    if (j < Hh) {
        unsigned int enc = d_g[b * Hh + j];
        sg[j] = fdec(enc) + bias[j];
        d_g[b * Hh + j] = 0u;               // restore sentinel
    }
    __syncthreads();
    float acc = b1[j];
#pragma unroll
    for (int k = 0; k < Hh; k++) acc += sg[k] * W1[k * D1 + j];
    d_h1[b * D1 + j] = fmaxf(acc, 0.0f);
}

// h2 = relu(h1 @ W2 + b2); 8 rows per block for W2 reuse
#define R2 8
__global__ void __launch_bounds__(512) k_mlp2(
    const float* __restrict__ W2, const float* __restrict__ b2)
{
    __shared__ float sh[R2 * D1];
    int j = threadIdx.x;
    int rb = blockIdx.x * R2;
    for (int i = j; i < R2 * D1; i += 512) sh[i] = d_h1[rb * D1 + i];
    __syncthreads();

    float acc[R2];
#pragma unroll
    for (int r = 0; r < R2; r++) acc[r] = b2[j];

    const float4* sh4 = (const float4*)sh;
#pragma unroll 4
    for (int k4 = 0; k4 < D1 / 4; k4++) {
        int k = k4 * 4;
        float w0 = W2[(k + 0) * D2 + j];
        float w1 = W2[(k + 1) * D2 + j];
        float w2 = W2[(k + 2) * D2 + j];
        float w3 = W2[(k + 3) * D2 + j];
#pragma unroll
        for (int r = 0; r < R2; r++) {
            float4 s = sh4[r * (D1 / 4) + k4];
            acc[r] += s.x * w0 + s.y * w1 + s.z * w2 + s.w * w3;
        }
    }
#pragma unroll
    for (int r = 0; r < R2; r++) d_h2[(rb + r) * D2 + j] = fmaxf(acc[r], 0.0f);
}

// out = h2 @ W3 + b3
__global__ void __launch_bounds__(128) k_mlp3(
    const float* __restrict__ W3, const float* __restrict__ b3,
    float* __restrict__ out)
{
    int b = blockIdx.x;
    int w = threadIdx.x >> 5;
    int lane = threadIdx.x & 31;
    float acc = 0.0f;
#pragma unroll
    for (int k = lane; k < D2; k += 32)
        acc += d_h2[b * D2 + k] * W3[k * D3 + w];
#pragma unroll
    for (int off = 16; off; off >>= 1) acc += __shfl_xor_sync(0xFFFFFFFFu, acc, off);
    if (lane == 0) out[b * D3 + w] = acc + b3[w];
}

// ---------------- launch -----------------------------------------------------
extern "C" void kernel_launch(void* const* d_in, const int* in_sizes, int n_in,
                              void* d_out, int out_size)
{
    const float* x    = (const float*)d_in[0];
    const int*   ei   = (const int*)  d_in[1];
    const int*   batch= (const int*)  d_in[2];
    const float* Wl   = (const float*)d_in[3];
    const float* Wr   = (const float*)d_in[4];
    const float* att  = (const float*)d_in[5];
    const float* bias = (const float*)d_in[6];
    const float* W1   = (const float*)d_in[7];
    const float* b1   = (const float*)d_in[8];
    const float* W2   = (const float*)d_in[9];
    const float* b2   = (const float*)d_in[10];
    const float* W3   = (const float*)d_in[11];
    const float* b3   = (const float*)d_in[12];
    float* out = (float*)d_out;

    k_count<<<(Ee / 16 + 255) / 256, 256>>>(ei);            // 1
    k_scan<<<NB, 1024>>>();                                 // 2
    k_transform<<<(Nn + 63) / 64, 256>>>(x, Wl, Wr);        // 3
    k_fill<<<(Ee / 16 + 255) / 256, 256>>>(ei);             // 4  <- profiled slot
    k_node<<<Nn / 8, 256>>>(att, batch);                    // 5
    k_mlp1<<<Bb, D1>>>(W1, b1, bias);                       // 6
    k_mlp2<<<Bb / R2, 512>>>(W2, b2);                       // 7
    k_mlp3<<<Bb, 128>>>(W3, b3, out);                       // 8
}

// round 15
// speedup vs baseline: 1.2613x; 1.2613x over previous
#include <cuda_runtime.h>
#include <math_constants.h>

// Problem constants (fixed by the reference)
#define Nn 100000
#define Ee 3200000
#define EN (Ee + Nn)      // edges + self loops
#define Hh 32
#define Ff 128
#define Bb 256
#define D1 1024
#define D2 512
#define D3 4
#define NB 98             // scan blocks: ceil(100000/1024)

// ---------------- scratch (static device globals; no allocation) -----------
// d_deg and d_g are zero at load; every kernel_launch call restores them to
// zero before finishing (k_node zeros d_deg, k_mlp1 zeros d_g) so graph
// replays are deterministic.
__device__ float        d_xl[Nn * Hh];       // x @ Wl
__device__ float        d_xr[Nn * Hh];       // x @ Wr
__device__ int          d_deg[Nn];           // raw in-degree (no self loop)
__device__ int          d_rowstart[Nn];      // CSR row offsets
__device__ int          d_cursor[Nn];        // fill cursors
__device__ int          d_csrc[EN];          // CSR source indices (by dst)
__device__ unsigned int d_g[Bb * Hh];        // pooled max per graph (encoded)
__device__ float        d_h1[Bb * D1];
__device__ float        d_h2[Bb * D2];

// order-preserving float<->unsigned encoding for atomicMax on floats.
// All real floats encode to >= 0x007FFFFF > 0, so zero-init is a valid
// "-inf" sentinel for atomicMax.
__device__ __forceinline__ unsigned int fenc(float f) {
    unsigned int u = __float_as_uint(f);
    return u ^ ((unsigned int)((int)u >> 31) | 0x80000000u);
}
__device__ __forceinline__ float fdec(unsigned int e) {
    unsigned int mask = ((int)e < 0) ? 0x80000000u : 0xFFFFFFFFu;
    return __uint_as_float(e ^ mask);
}

__device__ __forceinline__ int wscan_incl(int v, int lane) {
#pragma unroll
    for (int off = 1; off < 32; off <<= 1) {
        int n = __shfl_up_sync(0xFFFFFFFFu, v, off);
        if (lane >= off) v += n;
    }
    return v;
}

// ---------------- kernels ---------------------------------------------------

// degree histogram: 8 edges per thread (2x int4), fire-and-forget RED
__global__ void __launch_bounds__(256) k_count(const int* __restrict__ ei) {
    int i8 = blockIdx.x * blockDim.x + threadIdx.x;   // 0 .. Ee/8
    if (i8 >= Ee / 8) return;
    const int4* d4 = (const int4*)(ei + Ee);
    int4 a = d4[i8 * 2];
    int4 b = d4[i8 * 2 + 1];
    atomicAdd(&d_deg[a.x], 1);
    atomicAdd(&d_deg[a.y], 1);
    atomicAdd(&d_deg[a.z], 1);
    atomicAdd(&d_deg[a.w], 1);
    atomicAdd(&d_deg[b.x], 1);
    atomicAdd(&d_deg[b.y], 1);
    atomicAdd(&d_deg[b.z], 1);
    atomicAdd(&d_deg[b.w], 1);
}

// Single-kernel scan: each block recomputes its global prefix directly from
// raw d_deg (self-loops folded as +1/node), then intra-block scan ->
// rowstart, self-loop slot, cursor.
__global__ void __launch_bounds__(1024) k_scan() {
    __shared__ int wsum[32];
    __shared__ int s_pre;
    int t = threadIdx.x, lane = t & 31, w = t >> 5;
    int blockStart = blockIdx.x * 1024;
    int idx = blockStart + t;

    // prefix over preceding chunk: sum(deg[0..blockStart)) + blockStart (self loops)
    int a = 0;
    for (int k = t; k < blockStart; k += 1024) a += d_deg[k];
#pragma unroll
    for (int off = 16; off; off >>= 1) a += __shfl_xor_sync(0xFFFFFFFFu, a, off);
    if (lane == 0) wsum[w] = a;
    __syncthreads();
    if (w == 0) {
        int s = wsum[lane];
#pragma unroll
        for (int off = 16; off; off >>= 1) s += __shfl_xor_sync(0xFFFFFFFFu, s, off);
        if (lane == 0) s_pre = s + blockStart;
    }
    __syncthreads();

    int v = (idx < Nn) ? d_deg[idx] + 1 : 0;    // +1 self loop
    int incl = wscan_incl(v, lane);
    __syncthreads();
    if (lane == 31) wsum[w] = incl;
    __syncthreads();
    if (w == 0) wsum[lane] = wscan_incl(wsum[lane], lane);
    __syncthreads();
    int off = s_pre + ((w > 0) ? wsum[w - 1] : 0);
    int excl = off + incl - v;
    if (idx < Nn) {
        d_rowstart[idx] = excl;
        d_csrc[excl]    = idx;       // self loop first
        d_cursor[idx]   = excl + 1;
    }
}

// scatter real edges into CSR order: 8 edges per thread, 8 atomics in flight
__global__ void __launch_bounds__(256) k_fill(const int* __restrict__ ei) {
    int i8 = blockIdx.x * blockDim.x + threadIdx.x;
    if (i8 >= Ee / 8) return;
    const int4* s4 = (const int4*)ei;
    const int4* d4 = (const int4*)(ei + Ee);
    int4 sa = s4[i8 * 2], sb = s4[i8 * 2 + 1];
    int4 da = d4[i8 * 2], db = d4[i8 * 2 + 1];
    int p0 = atomicAdd(&d_cursor[da.x], 1);
    int p1 = atomicAdd(&d_cursor[da.y], 1);
    int p2 = atomicAdd(&d_cursor[da.z], 1);
    int p3 = atomicAdd(&d_cursor[da.w], 1);
    int p4 = atomicAdd(&d_cursor[db.x], 1);
    int p5 = atomicAdd(&d_cursor[db.y], 1);
    int p6 = atomicAdd(&d_cursor[db.z], 1);
    int p7 = atomicAdd(&d_cursor[db.w], 1);
    d_csrc[p0] = sa.x;
    d_csrc[p1] = sa.y;
    d_csrc[p2] = sa.z;
    d_csrc[p3] = sa.w;
    d_csrc[p4] = sb.x;
    d_csrc[p5] = sb.y;
    d_csrc[p6] = sb.z;
    d_csrc[p7] = sb.w;
}

// xl|xr = x @ [Wl|Wr]: 64 nodes x 64 cols per block, 256 threads,
// K processed in two 64-wide chunks -> 32KB smem -> high occupancy.
__global__ void __launch_bounds__(256) k_transform(
    const float* __restrict__ x,
    const float* __restrict__ Wl,
    const float* __restrict__ Wr)
{
    __shared__ float sW[64 * 64];   // [k_chunk][c]  16KB
    __shared__ float sx[64 * 64];   // [n][k_chunk]  16KB

    int t = threadIdx.x;
    int n0 = blockIdx.x * 64;               // grid 1563; last block ragged
    int tx = t & 15, ty = t >> 4;           // 16 x 16 thread grid
    int c0 = tx * 4;

    float acc[4][4] = {};

#pragma unroll
    for (int kc = 0; kc < 2; kc++) {
        int k0 = kc * 64;
        // load W chunk [64 x 64]
        for (int i = t; i < 64 * 64; i += 256) {
            int k = i >> 6, c = i & 63;
            sW[i] = (c < 32) ? Wl[(k0 + k) * Hh + c] : Wr[(k0 + k) * Hh + (c - 32)];
        }
        // load x chunk: 64 rows x 16 float4 (clamp ragged rows)
        {
            int f4 = t & 15;
            int rbase = t >> 4;
#pragma unroll
            for (int j = 0; j < 4; j++) {
                int r = rbase + j * 16;
                int row = min(n0 + r, Nn - 1);
                ((float4*)sx)[r * 16 + f4] =
                    *(const float4*)&x[(size_t)row * Ff + k0 + f4 * 4];
            }
        }
        __syncthreads();

        const float4* sW4 = (const float4*)sW;
        const float4* sx4 = (const float4*)sx;
#pragma unroll 4
        for (int k4 = 0; k4 < 16; k4++) {
            float4 w0 = sW4[(k4 * 4 + 0) * 16 + tx];
            float4 w1 = sW4[(k4 * 4 + 1) * 16 + tx];
            float4 w2 = sW4[(k4 * 4 + 2) * 16 + tx];
            float4 w3 = sW4[(k4 * 4 + 3) * 16 + tx];
#pragma unroll
            for (int i = 0; i < 4; i++) {
                float4 xv = sx4[(ty * 4 + i) * 16 + k4];
                acc[i][0] += xv.x * w0.x + xv.y * w1.x + xv.z * w2.x + xv.w * w3.x;
                acc[i][1] += xv.x * w0.y + xv.y * w1.y + xv.z * w2.y + xv.w * w3.y;
                acc[i][2] += xv.x * w0.z + xv.y * w1.z + xv.z * w2.z + xv.w * w3.z;
                acc[i][3] += xv.x * w0.w + xv.y * w1.w + xv.z * w2.w + xv.w * w3.w;
            }
        }
        __syncthreads();
    }

#pragma unroll
    for (int i = 0; i < 4; i++) {
        int node = n0 + ty * 4 + i;
        if (node < Nn) {
            float4 v = make_float4(acc[i][0], acc[i][1], acc[i][2], acc[i][3]);
            if (c0 < 32) *(float4*)&d_xl[node * Hh + c0] = v;
            else         *(float4*)&d_xr[node * Hh + (c0 - 32)] = v;
        }
    }
}

// Fused GATv2 edge phase v8: register tiles, csrc prefetch, 2-shuffle tile
// max. One warp per node; lane (g = row-subgroup, q = h-quad).
__global__ void __launch_bounds__(256, 4) k_node(
    const float* __restrict__ att, const int* __restrict__ batch)
{
    int t = threadIdx.x;
    int lane = t & 31;
    int w = t >> 5;

    int node = blockIdx.x * 8 + w;          // Nn % 8 == 0
    int beg = d_rowstart[node];
    int deg = d_deg[node];
    int end = beg + deg + 1;                // +1 self loop
    if (lane == 0) d_deg[node] = 0;         // restore for next replay

    int q = lane & 7;           // h-quad (h = 4q..4q+3)
    int g = lane >> 3;          // row subgroup 0..3
    float4 xr4  = *(const float4*)&d_xr[node * Hh + q * 4];
    float4 att4 = __ldg((const float4*)&att[q * 4]);

    float m = -CUDART_INF_F, zsum = 0.f;
    float4 acc = make_float4(0.f, 0.f, 0.f, 0.f);

    int myidx0 = beg + lane;
    int msrc = (myidx0 < end) ? __ldg(&d_csrc[myidx0]) : 0;

    for (int j0 = beg; j0 < end; j0 += 32) {
        int cnt = end - j0;                  // valid rows are r < cnt

        // prefetch next tile's sources (off the critical path)
        int nidx = j0 + 32 + lane;
        int msrc_next = (nidx < end) ? __ldg(&d_csrc[nidx]) : 0;

        // ---- stage into registers: 8 independent LDG.128 ----
        float4 v[8];
#pragma unroll
        for (int i = 0; i < 8; i++) {
            int r = i * 4 + g;
            int src = __shfl_sync(0xFFFFFFFFu, msrc, r);
            v[i] = make_float4(0.f, 0.f, 0.f, 0.f);
            if (r < cnt) v[i] = *(const float4*)&d_xl[src * Hh + q * 4];
        }

        // ---- partial scores from this lane's quad ----
        float s[8];
#pragma unroll
        for (int i = 0; i < 8; i++) {
            float u, sc;
            float a0 = v[i].x + xr4.x; u = fmaxf(a0, 0.2f * a0); sc  = u * att4.x;
            float a1 = v[i].y + xr4.y; u = fmaxf(a1, 0.2f * a1); sc += u * att4.y;
            float a2 = v[i].z + xr4.z; u = fmaxf(a2, 0.2f * a2); sc += u * att4.z;
            float a3 = v[i].w + xr4.w; u = fmaxf(a3, 0.2f * a3); sc += u * att4.w;
            s[i] = sc;
        }
        // reduce across the 8 q-lanes sharing this g (xor 1,2,4)
#pragma unroll
        for (int off = 1; off <= 4; off <<= 1) {
#pragma unroll
            for (int i = 0; i < 8; i++)
                s[i] += __shfl_xor_sync(0xFFFFFFFFu, s[i], off);
        }
        // mask invalid rows
#pragma unroll
        for (int i = 0; i < 8; i++)
            if (i * 4 + g >= cnt) s[i] = -CUDART_INF_F;

        // ---- tile max: scores q-duplicated -> local max + cross-g xor 8,16 ----
        float mt = s[0];
#pragma unroll
        for (int i = 1; i < 8; i++) mt = fmaxf(mt, s[i]);
        mt = fmaxf(mt, __shfl_xor_sync(0xFFFFFFFFu, mt, 8));
        mt = fmaxf(mt, __shfl_xor_sync(0xFFFFFFFFu, mt, 16));
        float mnew = fmaxf(m, mt);
        float scale = __expf(m - mnew);      // first tile: exp(-inf)=0

        // ---- exp + z ----
        float zp = 0.f;
#pragma unroll
        for (int i = 0; i < 8; i++) {
            float p = __expf(s[i] - mnew);   // masked rows -> 0
            s[i] = p;
            zp += p;
        }
        zp += __shfl_xor_sync(0xFFFFFFFFu, zp, 8);
        zp += __shfl_xor_sync(0xFFFFFFFFu, zp, 16);
        zsum = zsum * scale + zp;

        // ---- aggregate in registers ----
        acc.x *= scale; acc.y *= scale; acc.z *= scale; acc.w *= scale;
#pragma unroll
        for (int i = 0; i < 8; i++) {
            acc.x += s[i] * v[i].x;
            acc.y += s[i] * v[i].y;
            acc.z += s[i] * v[i].z;
            acc.w += s[i] * v[i].w;
        }
        m = mnew;
        msrc = msrc_next;
    }

    // combine across row subgroups (lanes l, l^8, l^16 share quad q)
#pragma unroll
    for (int off = 8; off <= 16; off <<= 1) {
        acc.x += __shfl_xor_sync(0xFFFFFFFFu, acc.x, off);
        acc.y += __shfl_xor_sync(0xFFFFFFFFu, acc.y, off);
        acc.z += __shfl_xor_sync(0xFFFFFFFFu, acc.z, off);
        acc.w += __shfl_xor_sync(0xFFFFFFFFu, acc.w, off);
    }
    float inv = 1.0f / zsum;
    float compo = (g == 0) ? acc.x : (g == 1) ? acc.y : (g == 2) ? acc.z : acc.w;
    float out = compo * inv;                 // acc holds p*xl directly
    int h = q * 4 + g;
    int bg = __ldg(&batch[node]);
    atomicMax(&d_g[bg * Hh + h], fenc(out));
}

// h1 = relu((g + bias) @ W1 + b1); also restores d_g to 0 for next replay
__global__ void __launch_bounds__(1024) k_mlp1(
    const float* __restrict__ W1, const float* __restrict__ b1,
    const float* __restrict__ bias)
{
    __shared__ float sg[Hh];
    int b = blockIdx.x;
    int j = threadIdx.x;
    if (j < Hh) {
        unsigned int enc = d_g[b * Hh + j];
        sg[j] = fdec(enc) + bias[j];
        d_g[b * Hh + j] = 0u;               // restore sentinel
    }
    __syncthreads();
    float acc = b1[j];
#pragma unroll
    for (int k = 0; k < Hh; k++) acc += sg[k] * W1[k * D1 + j];
    d_h1[b * D1 + j] = fmaxf(acc, 0.0f);
}

// h2 = relu(h1 @ W2 + b2); 4 rows per block for W2 reuse
#define R2 4
__global__ void __launch_bounds__(512) k_mlp2(
    const float* __restrict__ W2, const float* __restrict__ b2)
{
    __shared__ float sh[R2 * D1];
    int j = threadIdx.x;
    int rb = blockIdx.x * R2;
    for (int i = j; i < R2 * D1; i += 512) sh[i] = d_h1[rb * D1 + i];
    __syncthreads();

    float acc[R2];
#pragma unroll
    for (int r = 0; r < R2; r++) acc[r] = b2[j];

    const float4* sh4 = (const float4*)sh;
#pragma unroll 4
    for (int k4 = 0; k4 < D1 / 4; k4++) {
        int k = k4 * 4;
        float w0 = W2[(k + 0) * D2 + j];
        float w1 = W2[(k + 1) * D2 + j];
        float w2 = W2[(k + 2) * D2 + j];
        float w3 = W2[(k + 3) * D2 + j];
#pragma unroll
        for (int r = 0; r < R2; r++) {
            float4 s = sh4[r * (D1 / 4) + k4];
            acc[r] += s.x * w0 + s.y * w1 + s.z * w2 + s.w * w3;
        }
    }
#pragma unroll
    for (int r = 0; r < R2; r++) d_h2[(rb + r) * D2 + j] = fmaxf(acc[r], 0.0f);
}

// out = h2 @ W3 + b3
__global__ void __launch_bounds__(128) k_mlp3(
    const float* __restrict__ W3, const float* __restrict__ b3,
    float* __restrict__ out)
{
    int b = blockIdx.x;
    int w = threadIdx.x >> 5;
    int lane = threadIdx.x & 31;
    float acc = 0.0f;
#pragma unroll
    for (int k = lane; k < D2; k += 32)
        acc += d_h2[b * D2 + k] * W3[k * D3 + w];
#pragma unroll
    for (int off = 16; off; off >>= 1) acc += __shfl_xor_sync(0xFFFFFFFFu, acc, off);
    if (lane == 0) out[b * D3 + w] = acc + b3[w];
}

// ---------------- launch -----------------------------------------------------
extern "C" void kernel_launch(void* const* d_in, const int* in_sizes, int n_in,
                              void* d_out, int out_size)
{
    const float* x    = (const float*)d_in[0];
    const int*   ei   = (const int*)  d_in[1];
    const int*   batch= (const int*)  d_in[2];
    const float* Wl   = (const float*)d_in[3];
    const float* Wr   = (const float*)d_in[4];
    const float* att  = (const float*)d_in[5];
    const float* bias = (const float*)d_in[6];
    const float* W1   = (const float*)d_in[7];
    const float* b1   = (const float*)d_in[8];
    const float* W2   = (const float*)d_in[9];
    const float* b2   = (const float*)d_in[10];
    const float* W3   = (const float*)d_in[11];
    const float* b3   = (const float*)d_in[12];
    float* out = (float*)d_out;

    // Secondary stream + fork/join events (host-side objects, created once;
    // no device memory involved). Same work is performed on every call.
    static cudaStream_t s1 = nullptr;
    static cudaEvent_t evFork = nullptr, evJoin = nullptr;
    if (s1 == nullptr) {
        cudaStreamCreateWithFlags(&s1, cudaStreamNonBlocking);
        cudaEventCreateWithFlags(&evFork, cudaEventDisableTiming);
        cudaEventCreateWithFlags(&evJoin, cudaEventDisableTiming);
    }

    // ---- fork: transform (compute-bound) runs concurrently with the
    //      CSR build chain (LTS/atomic-bound) ----
    cudaEventRecord(evFork, 0);
    cudaStreamWaitEvent(s1, evFork, 0);

    k_transform<<<(Nn + 63) / 64, 256, 0, s1>>>(x, Wl, Wr);   // launch 1 (s1)

    k_count<<<(Ee / 8 + 255) / 256, 256>>>(ei);               // launch 2
    k_scan<<<NB, 1024>>>();                                   // launch 3
    k_fill<<<(Ee / 8 + 255) / 256, 256>>>(ei);                // launch 4 <- profiled

    // ---- join: node needs both transform and CSR ----
    cudaEventRecord(evJoin, s1);
    cudaStreamWaitEvent(0, evJoin, 0);

    k_node<<<Nn / 8, 256>>>(att, batch);                      // launch 5
    k_mlp1<<<Bb, D1>>>(W1, b1, bias);                         // launch 6
    k_mlp2<<<Bb / R2, 512>>>(W2, b2);                         // launch 7
    k_mlp3<<<Bb, 128>>>(W3, b3, out);                         // launch 8
}